// round 17
// baseline (speedup 1.0000x reference)
#include <cuda_runtime.h>
#include <math.h>
#include <stdint.h>

#define BSZ 512
#define DSZ 256
#define EPSF 1e-8f
#define MARGINF 0.3f
#define UWF 0.05f

// ---------------------------------------------------------------------------
// scratch (__device__ globals; no cudaMalloc allowed)
// ---------------------------------------------------------------------------
__device__ float g_bl[128], g_bv[128], g_bu[128];
__device__ unsigned int g_ctr = 0;               // wraps via atomicInc(.,127)

// packed f32x2 FMA: d = a*b + d (lane-wise IEEE fma)
#define FMA2(d, a, b) \
    asm("fma.rn.f32x2 %0, %1, %2, %0;" : "+l"(d) : "l"(a), "l"(b))

__device__ __forceinline__ uint32_t smem_u32(const void* p) {
    uint32_t r;
    asm("{ .reg .u64 t; cvta.to.shared.u64 t, %1; cvt.u32.u64 %0, t; }"
        : "=r"(r) : "l"(p));
    return r;
}

// ---------------------------------------------------------------------------
// Single fused kernel: anchor-parallel. 128 blocks x 128 threads.
// Block owns anchors i0..i0+3; streams ALL 512 j-rows through double-buffered
// smem (16-d chunks); mines pos/neg block-locally; finalizes its 4 anchors;
// atomicInc scalar tail. NO cross-block sync anywhere except the tail.
// ---------------------------------------------------------------------------
__global__ __launch_bounds__(128) void k_all(const float* __restrict__ E,
                                             const float* __restrict__ U,
                                             const int*   __restrict__ L,
                                             float* __restrict__ out) {
    __shared__ __align__(16) float2 Aw[256][4];   // dup'd anchors: [d][a]={v,v}
    __shared__ __align__(16) float  Bs[2][16][258]; // double-buffered j-stage
    __shared__ int   slab[512];
    __shared__ float s_nap[4][4];                 // warp partials of anchor norms
    __shared__ float s_na[4];
    __shared__ unsigned long long s_mp[4][4], s_mn[4][4];
    __shared__ unsigned long long s_bestp[4], s_bestn[4];
    __shared__ float s_al[4], s_av[4], s_us[4];
    __shared__ int   s_islast;
    __shared__ float s_red[12];

    const int t = threadIdx.x;
    const int w = t >> 5, lane = t & 31;
    const int bid = blockIdx.x;
    const int i0 = bid * 4;
    const float4* E4 = (const float4*)E;
    const float4* U4 = (const float4*)U;

    // ---- labels ----
    slab[t]       = L[t];
    slab[t + 128] = L[t + 128];
    slab[t + 256] = L[t + 256];
    slab[t + 384] = L[t + 384];

    // ---- stage anchors (dup'd) + norm partials ----
    float nap[4];
#pragma unroll
    for (int a = 0; a < 4; a++) {
        int ia = i0 + a;
        float v0 = E[ia * DSZ + t];
        float v1 = E[ia * DSZ + t + 128];
        float2 d0; d0.x = d0.y = v0; Aw[t][a] = d0;
        float2 d1; d1.x = d1.y = v1; Aw[t + 128][a] = d1;
        nap[a] = fmaf(v0, v0, v1 * v1);
    }
#pragma unroll
    for (int off = 16; off; off >>= 1)
#pragma unroll
        for (int a = 0; a < 4; a++)
            nap[a] += __shfl_down_sync(0xffffffffu, nap[a], off);
    if (lane == 0)
#pragma unroll
        for (int a = 0; a < 4; a++) s_nap[w][a] = nap[a];

    // ---- prefetch B stage 0 (pass 0, chunk 0): thread's j-pair rows ----
    float4 pj[8];
    {
        int j0g = 2 * t, j1g = 2 * t + 1;
#pragma unroll
        for (int k = 0; k < 4; k++) {
            pj[k]     = E4[j0g * 64 + k];
            pj[4 + k] = E4[j1g * 64 + k];
        }
    }
    __syncthreads();      // Aw, slab, s_nap visible
    if (t < 4) s_na[t] = s_nap[0][t] + s_nap[1][t] + s_nap[2][t] + s_nap[3][t];

    int la[4];
#pragma unroll
    for (int a = 0; a < 4; a++) la[a] = slab[i0 + a];

    // STS stage 0 into buf 0
#pragma unroll
    for (int e = 0; e < 2; e++)
#pragma unroll
        for (int k = 0; k < 4; k++) {
            float4 v = pj[e * 4 + k];
            Bs[0][k * 4 + 0][2 * t + e] = v.x;
            Bs[0][k * 4 + 1][2 * t + e] = v.y;
            Bs[0][k * 4 + 2][2 * t + e] = v.z;
            Bs[0][k * 4 + 3][2 * t + e] = v.w;
        }
    __syncthreads();

    const uint32_t aw0 = smem_u32(&Aw[0][0]);
    const uint32_t bs0 = smem_u32(&Bs[0][0][0]) + 8 * t;

    uint64_t acc[4] = {0, 0, 0, 0}, accN = 0;
    unsigned long long bp[4] = {0, 0, 0, 0};
    unsigned long long bn[4] = {~0ull, ~0ull, ~0ull, ~0ull};

#pragma unroll 1
    for (int s = 0; s < 32; s++) {
        const int p = s >> 4;          // j-pass
        const int c = s & 15;          // d-chunk
        const int buf = s & 1;

        if (s < 31) {                  // prefetch next stage
            const int pn = (s + 1) >> 4, cn = (s + 1) & 15;
            const int j0g = pn * 256 + 2 * t, j1g = j0g + 1;
#pragma unroll
            for (int k = 0; k < 4; k++) {
                pj[k]     = E4[j0g * 64 + cn * 4 + k];
                pj[4 + k] = E4[j1g * 64 + cn * 4 + k];
            }
        }

        // compute 16 d from current buffer
        const uint32_t bsc = bs0 + buf * 16512;
        const uint32_t awc = aw0 + c * 512;
#pragma unroll
        for (int dl = 0; dl < 16; dl++) {
            uint64_t aa0, aa1, aa2, aa3, j01;
            asm("ld.shared.v2.u64 {%0, %1}, [%2];"
                : "=l"(aa0), "=l"(aa1) : "r"(awc + dl * 32));
            asm("ld.shared.v2.u64 {%0, %1}, [%2];"
                : "=l"(aa2), "=l"(aa3) : "r"(awc + dl * 32 + 16));
            asm("ld.shared.b64 %0, [%1];"
                : "=l"(j01) : "r"(bsc + dl * 1032));
            FMA2(acc[0], aa0, j01);
            FMA2(acc[1], aa1, j01);
            FMA2(acc[2], aa2, j01);
            FMA2(acc[3], aa3, j01);
            FMA2(accN, j01, j01);
        }

        if (s < 31) {                  // store next stage into other buffer
            const int nb = (s + 1) & 1;
#pragma unroll
            for (int e = 0; e < 2; e++)
#pragma unroll
                for (int k = 0; k < 4; k++) {
                    float4 v = pj[e * 4 + k];
                    Bs[nb][k * 4 + 0][2 * t + e] = v.x;
                    Bs[nb][k * 4 + 1][2 * t + e] = v.y;
                    Bs[nb][k * 4 + 2][2 * t + e] = v.z;
                    Bs[nb][k * 4 + 3][2 * t + e] = v.w;
                }
        }

        if (c == 15) {                 // end of pass: mine this thread's 2 j's
            uint32_t lo, hi;
            asm("mov.b64 {%0, %1}, %2;" : "=r"(lo), "=r"(hi) : "l"(accN));
            const float nj0 = __uint_as_float(lo);
            const float nj1 = __uint_as_float(hi);
            const int jg0 = p * 256 + 2 * t, jg1 = jg0 + 1;
            const int lj0 = slab[jg0], lj1 = slab[jg1];
#pragma unroll
            for (int a = 0; a < 4; a++) {
                asm("mov.b64 {%0, %1}, %2;" : "=r"(lo), "=r"(hi) : "l"(acc[a]));
                const float dd0 = __uint_as_float(lo);
                const float dd1 = __uint_as_float(hi);
                const float na = s_na[a];
                const int ia = i0 + a;
                float dist0 = sqrtf(fmaxf(na + nj0 - 2.f * dd0, 0.f)) + EPSF;
                float dist1 = sqrtf(fmaxf(na + nj1 - 2.f * dd1, 0.f)) + EPSF;
                unsigned long long e0 =
                    ((unsigned long long)__float_as_uint(dist0) << 32);
                unsigned long long e1 =
                    ((unsigned long long)__float_as_uint(dist1) << 32);
                if (lj0 == la[a] && jg0 != ia) {
                    unsigned long long cnd = e0 | (0xFFFFFFFFu - (unsigned)jg0);
                    if (cnd > bp[a]) bp[a] = cnd;
                }
                if (lj1 == la[a] && jg1 != ia) {
                    unsigned long long cnd = e1 | (0xFFFFFFFFu - (unsigned)jg1);
                    if (cnd > bp[a]) bp[a] = cnd;
                }
                if (lj0 != la[a]) {
                    unsigned long long cnd = e0 | (unsigned)jg0;
                    if (cnd < bn[a]) bn[a] = cnd;
                }
                if (lj1 != la[a]) {
                    unsigned long long cnd = e1 | (unsigned)jg1;
                    if (cnd < bn[a]) bn[a] = cnd;
                }
                acc[a] = 0;
            }
            accN = 0;
        }
        __syncthreads();
    }

    // ---- block-local mining reduction ----
#pragma unroll
    for (int a = 0; a < 4; a++) {
#pragma unroll
        for (int off = 16; off; off >>= 1) {
            unsigned long long o = __shfl_down_sync(0xffffffffu, bp[a], off);
            if (o > bp[a]) bp[a] = o;
            o = __shfl_down_sync(0xffffffffu, bn[a], off);
            if (o < bn[a]) bn[a] = o;
        }
        if (lane == 0) { s_mp[w][a] = bp[a]; s_mn[w][a] = bn[a]; }
    }
    __syncthreads();
    if (t < 4) {
        unsigned long long P = s_mp[0][t], N = s_mn[0][t];
#pragma unroll
        for (int k = 1; k < 4; k++) {
            if (s_mp[k][t] > P) P = s_mp[k][t];
            if (s_mn[k][t] < N) N = s_mn[k][t];
        }
        s_bestp[t] = P; s_bestn[t] = N;
    }
    __syncthreads();

    // ---- finalize: warp w -> anchor i0+w (half-warp per side) ----
    {
        const int ia = i0 + w;
        const int side = lane >> 4;
        const int l16 = lane & 15;
        const unsigned long long ppos = s_bestp[w];
        const unsigned long long pneg = s_bestn[w];
        const bool valid = (ppos != 0ull) && (pneg != ~0ull);
        const float dp = __uint_as_float((uint32_t)(ppos >> 32));
        const float dn = __uint_as_float((uint32_t)(pneg >> 32));
        const int jp = (ppos != 0ull) ? (int)(0xFFFFFFFFu - (uint32_t)ppos) : 0;
        const int jn = (pneg != ~0ull) ? (int)(uint32_t)pneg : 0;
        const int jx = side ? jn : jp;

        float W = 0.f, us = 0.f;
#pragma unroll
        for (int k = 0; k < 4; k++) {
            int q = l16 + 16 * k;
            float4 ui = U4[ia * 64 + q];
            float4 ei = E4[ia * 64 + q];
            float4 ej = E4[jx * 64 + q];
            ui.x = fminf(fmaxf(ui.x, 1e-6f), 1.f);   // clip; NaN -> 1e-6
            ui.y = fminf(fmaxf(ui.y, 1e-6f), 1.f);
            ui.z = fminf(fmaxf(ui.z, 1e-6f), 1.f);
            ui.w = fminf(fmaxf(ui.w, 1e-6f), 1.f);
            float df;
            df = ei.x - ej.x; W = fmaf(ui.x * ui.x, df * df, W);
            df = ei.y - ej.y; W = fmaf(ui.y * ui.y, df * df, W);
            df = ei.z - ej.z; W = fmaf(ui.z * ui.z, df * df, W);
            df = ei.w - ej.w; W = fmaf(ui.w * ui.w, df * df, W);
            if (side == 0) us += ((ui.x + ui.y) + (ui.z + ui.w));
        }
#pragma unroll
        for (int off = 8; off; off >>= 1) {
            W  += __shfl_xor_sync(0xffffffffu, W, off, 16);
            us += __shfl_xor_sync(0xffffffffu, us, off, 16);
        }
        float Wn = __shfl_sync(0xffffffffu, W, 16);
        if (lane == 0) {
            float up2 = W / (dp * dp) + EPSF;
            float un2 = Wn / (dn * dn) + EPSF;
            float sig = sqrtf(up2 + un2 + EPSF);
            float me = MARGINF + UWF * sig;
            float z = (dp - dn + me) / sig;
            float sp = fmaxf(z, 0.f) + log1pf(expf(-fabsf(z)));
            s_al[w] = valid ? sig * sp : 0.f;
            s_av[w] = valid ? 1.f : 0.f;
            s_us[w] = us;
        }
    }
    __syncthreads();

    if (t == 0) {
        g_bl[bid] = (s_al[0] + s_al[1]) + (s_al[2] + s_al[3]);
        g_bv[bid] = (s_av[0] + s_av[1]) + (s_av[2] + s_av[3]);
        g_bu[bid] = (s_us[0] + s_us[1]) + (s_us[2] + s_us[3]);
        __threadfence();
        s_islast = (atomicInc(&g_ctr, 127) == 127) ? 1 : 0;
    }
    __syncthreads();
    if (!s_islast) return;
    __threadfence();

    // ---- globally last block: reduce 128 partials -> scalar ----
    {
        float l = *(volatile float*)&g_bl[t];
        float v = *(volatile float*)&g_bv[t];
        float u = *(volatile float*)&g_bu[t];
#pragma unroll
        for (int off = 16; off; off >>= 1) {
            l += __shfl_down_sync(0xffffffffu, l, off);
            v += __shfl_down_sync(0xffffffffu, v, off);
            u += __shfl_down_sync(0xffffffffu, u, off);
        }
        if (lane == 0) { s_red[w] = l; s_red[4 + w] = v; s_red[8 + w] = u; }
        __syncthreads();
        if (t == 0) {
            float Lx = (s_red[0] + s_red[1]) + (s_red[2] + s_red[3]);
            float V  = (s_red[4] + s_red[5]) + (s_red[6] + s_red[7]);
            float Uu = (s_red[8] + s_red[9]) + (s_red[10] + s_red[11]);
            float total = Lx / fmaxf(V, 1.0f) + UWF * (Uu / (float)(BSZ * DSZ));
            if (isnan(total) || isinf(total)) total = 0.f;
            out[0] = total;
        }
    }
}

// ---------------------------------------------------------------------------
extern "C" void kernel_launch(void* const* d_in, const int* in_sizes, int n_in,
                              void* d_out, int out_size) {
    const float* E = (const float*)d_in[0];
    const float* U = (const float*)d_in[1];
    const int*   L = (const int*)d_in[2];
    float* out = (float*)d_out;

    k_all<<<128, 128>>>(E, U, L, out);
}